// round 2
// baseline (speedup 1.0000x reference)
#include <cuda_runtime.h>
#include <cstdint>
#include <math.h>

#define DEVI __device__ __forceinline__

static constexpr int BDIM  = 4096;
static constexpr int INDIM = 1024;
static constexpr int HDIM  = 2048;
static constexpr int KDIM  = HDIM + INDIM;        // 3072
static constexpr int MT  = 128;                   // CTA M tile
static constexpr int NG  = 64;                    // CTA N tile per gate
static constexpr int NTT = 4 * NG;                // 256 total N rows in smem
static constexpr int KT  = 32;                    // K chunk (floats) = 128B row
static constexpr int NCHUNK = KDIM / KT;          // 96
static constexpr int STAGES = 3;
static constexpr int A_BYTES   = MT  * 128;       // 16384
static constexpr int B_BYTES   = NTT * 128;       // 32768
static constexpr int STG_BYTES = A_BYTES + B_BYTES;   // 49152
static constexpr int SMEM_TOTAL = STAGES * STG_BYTES; // 147456

// tf32-rounded, k-permuted scratch (device globals: allocation-free)
__device__ __align__(1024) float g_A[(size_t)BDIM * KDIM];      // [B][K]  (hx concat)
__device__ __align__(1024) float g_W[(size_t)4 * HDIM * KDIM];  // [4][H][K]

// ---------------- helpers ----------------
DEVI uint32_t smem_u32(const void* p) {
    uint32_t a;
    asm("{ .reg .u64 t; cvta.to.shared.u64 t, %1; cvt.u32.u64 %0, t; }" : "=r"(a) : "l"(p));
    return a;
}
DEVI float to_tf32(float x) {
    uint32_t u;
    asm("cvt.rna.tf32.f32 %0, %1;" : "=r"(u) : "f"(x));
    return __uint_as_float(u);
}
DEVI void cp16(uint32_t dst, const float* src) {
    asm volatile("cp.async.cg.shared.global [%0], [%1], 16;" :: "r"(dst), "l"(src) : "memory");
}
DEVI void cp_commit() { asm volatile("cp.async.commit_group;" ::: "memory"); }
DEVI void cp_wait1()  { asm volatile("cp.async.wait_group 1;" ::: "memory"); }
DEVI void cp_wait0()  { asm volatile("cp.async.wait_group 0;" ::: "memory"); }

DEVI float2 lds64(uint32_t a) {
    float2 v;
    asm("ld.shared.v2.f32 {%0,%1}, [%2];" : "=f"(v.x), "=f"(v.y) : "r"(a));
    return v;
}
DEVI void mma8(float* d, float2 alo, float2 ahi, float2 b) {
    asm("mma.sync.aligned.m16n8k8.row.col.f32.tf32.tf32.f32 "
        "{%0,%1,%2,%3}, {%4,%5,%6,%7}, {%8,%9}, {%0,%1,%2,%3};"
        : "+f"(d[0]), "+f"(d[1]), "+f"(d[2]), "+f"(d[3])
        : "r"(__float_as_uint(alo.x)), "r"(__float_as_uint(ahi.x)),
          "r"(__float_as_uint(alo.y)), "r"(__float_as_uint(ahi.y)),
          "r"(__float_as_uint(b.x)),   "r"(__float_as_uint(b.y)));
}
DEVI float sigmoidf_(float x) { return __fdividef(1.0f, 1.0f + __expf(-x)); }
DEVI float tanhf_(float x)    { return 2.0f * sigmoidf_(2.0f * x) - 1.0f; }

// ------------- prep: tf32-round + k-permute ([0,4,1,5,2,6,3,7] per k8 group) -------------
__global__ void prep_A(const float* __restrict__ x, const float* __restrict__ ph) {
    const int ngrp = BDIM * (KDIM / 8);
    for (int i = blockIdx.x * blockDim.x + threadIdx.x; i < ngrp;
         i += gridDim.x * blockDim.x) {
        int b   = i / (KDIM / 8);
        int k0  = (i - b * (KDIM / 8)) * 8;
        const float* src = (k0 < HDIM) ? (ph + (size_t)b * HDIM + k0)
                                       : (x  + (size_t)b * INDIM + (k0 - HDIM));
        float4 lo = ((const float4*)src)[0];
        float4 hi = ((const float4*)src)[1];
        float4 o0 = make_float4(to_tf32(lo.x), to_tf32(hi.x), to_tf32(lo.y), to_tf32(hi.y));
        float4 o1 = make_float4(to_tf32(lo.z), to_tf32(hi.z), to_tf32(lo.w), to_tf32(hi.w));
        float4* dst = (float4*)(g_A + (size_t)b * KDIM + k0);
        dst[0] = o0; dst[1] = o1;
    }
}
__global__ void prep_W(const float* __restrict__ Wi, const float* __restrict__ Wf,
                       const float* __restrict__ Wo, const float* __restrict__ Wc) {
    const int per_gate = HDIM * (KDIM / 8);
    const int ngrp = 4 * per_gate;
    for (int i = blockIdx.x * blockDim.x + threadIdx.x; i < ngrp;
         i += gridDim.x * blockDim.x) {
        int g   = i / per_gate;
        int off = i - g * per_gate;
        const float* W = (g == 0) ? Wi : (g == 1) ? Wf : (g == 2) ? Wo : Wc;
        const float* src = W + (size_t)off * 8;
        float4 lo = ((const float4*)src)[0];
        float4 hi = ((const float4*)src)[1];
        float4 o0 = make_float4(to_tf32(lo.x), to_tf32(hi.x), to_tf32(lo.y), to_tf32(hi.y));
        float4 o1 = make_float4(to_tf32(lo.z), to_tf32(hi.z), to_tf32(lo.w), to_tf32(hi.w));
        float4* dst = (float4*)(g_W + (size_t)g * HDIM * KDIM + (size_t)off * 8);
        dst[0] = o0; dst[1] = o1;
    }
}

// ---------------- main fused LSTM GEMM (mma.sync tf32) ----------------
__global__ __launch_bounds__(256, 1)
void lstm_main(const float* __restrict__ prev_c, float* __restrict__ out) {
    extern __shared__ char smem[];
    const uint32_t sb = smem_u32(smem);
    const int tid  = threadIdx.x;
    const int lane = tid & 31;
    const int wid  = tid >> 5;
    const int warp_m = wid & 1;        // 2 warps over M (64 rows each)
    const int warp_n = wid >> 1;       // 4 warps over N (16 cols/gate each)
    const int q   = lane >> 2;         // 0..7
    const int cid = lane & 3;          // 0..3
    const int m0 = blockIdx.x * MT;
    const int n0 = blockIdx.y * NG;

    // ---- cp.async slot setup (12 x 16B per thread per stage) ----
    const float* a_src[4]; uint32_t a_dst[4];
#pragma unroll
    for (int it = 0; it < 4; it++) {
        int i = tid + 256 * it;
        int row = i >> 3, u = i & 7;
        a_src[it] = g_A + (size_t)(m0 + row) * KDIM + u * 4;
        a_dst[it] = sb + row * 128 + (((u ^ (row & 7))) << 4);
    }
    const float* b_src[8]; uint32_t b_dst[8];
#pragma unroll
    for (int it = 0; it < 8; it++) {
        int i = tid + 256 * it;
        int row = i >> 3, u = i & 7;       // row: gate*64 + n_local
        int gate = row >> 6, nl = row & 63;
        b_src[it] = g_W + ((size_t)gate * HDIM + (n0 + nl)) * KDIM + u * 4;
        b_dst[it] = sb + A_BYTES + row * 128 + (((u ^ (row & 7))) << 4);
    }

    // ---- fragment base addresses (kk-step applied as ^ (kk<<5)) ----
    uint32_t aaddr[4][2];
#pragma unroll
    for (int mt = 0; mt < 4; mt++)
#pragma unroll
        for (int h = 0; h < 2; h++) {
            int row = warp_m * 64 + mt * 16 + q + 8 * h;
            aaddr[mt][h] = sb + row * 128 +
                           ((((cid >> 1) ^ (row & 7))) << 4) + 8 * (cid & 1);
        }
    uint32_t baddr[4][2];
#pragma unroll
    for (int g = 0; g < 4; g++)
#pragma unroll
        for (int nt = 0; nt < 2; nt++) {
            int row = g * 64 + warp_n * 16 + nt * 8 + q;
            baddr[g][nt] = sb + A_BYTES + row * 128 +
                           ((((cid >> 1) ^ (row & 7))) << 4) + 8 * (cid & 1);
        }

    float acc[4][4][2][4];
#pragma unroll
    for (int g = 0; g < 4; g++)
#pragma unroll
        for (int mt = 0; mt < 4; mt++)
#pragma unroll
            for (int nt = 0; nt < 2; nt++)
#pragma unroll
                for (int e = 0; e < 4; e++) acc[g][mt][nt][e] = 0.0f;

    auto load_stage = [&](int chunk, int s) {
        const uint32_t so = (uint32_t)(s * STG_BYTES);
        const int ko = chunk * KT;
#pragma unroll
        for (int it = 0; it < 4; it++) cp16(a_dst[it] + so, a_src[it] + ko);
#pragma unroll
        for (int it = 0; it < 8; it++) cp16(b_dst[it] + so, b_src[it] + ko);
        cp_commit();
    };

    // prologue: stages 0,1
    load_stage(0, 0);
    load_stage(1, 1);

    for (int c = 0; c < NCHUNK; c++) {
        if (c == NCHUNK - 1) cp_wait0(); else cp_wait1();
        __syncthreads();

        if (c + 2 < NCHUNK) load_stage(c + 2, (c + 2) % STAGES);

        const uint32_t so = (uint32_t)((c % STAGES) * STG_BYTES);
#pragma unroll
        for (int kk = 0; kk < 4; kk++) {
            const uint32_t kx = (uint32_t)(kk << 5);
            float2 af[4][2];
#pragma unroll
            for (int mt = 0; mt < 4; mt++) {
                af[mt][0] = lds64((aaddr[mt][0] + so) ^ kx);
                af[mt][1] = lds64((aaddr[mt][1] + so) ^ kx);
            }
            float2 bf[4][2];
#pragma unroll
            for (int g = 0; g < 4; g++) {
                bf[g][0] = lds64((baddr[g][0] + so) ^ kx);
                bf[g][1] = lds64((baddr[g][1] + so) ^ kx);
            }
#pragma unroll
            for (int g = 0; g < 4; g++)
#pragma unroll
                for (int nt = 0; nt < 2; nt++)
#pragma unroll
                    for (int mt = 0; mt < 4; mt++)
                        mma8(acc[g][mt][nt], af[mt][0], af[mt][1], bf[g][nt]);
        }
        __syncthreads();
    }

    // -------- fused LSTM epilogue (register-wise across gates) --------
#pragma unroll
    for (int mt = 0; mt < 4; mt++)
#pragma unroll
        for (int h = 0; h < 2; h++) {
            const int b = m0 + warp_m * 64 + mt * 16 + q + 8 * h;
            const float* pc = prev_c + (size_t)b * HDIM;
            float* oh = out + (size_t)b * HDIM;
            float* oc = out + (size_t)(BDIM + b) * HDIM;
#pragma unroll
            for (int nt = 0; nt < 2; nt++) {
                const int n = n0 + warp_n * 16 + nt * 8 + 2 * cid;
                float2 pcv = *(const float2*)(pc + n);
                float hv[2], cv[2];
#pragma unroll
                for (int e = 0; e < 2; e++) {
                    const float gi = acc[0][mt][nt][2 * h + e];
                    const float gf = acc[1][mt][nt][2 * h + e];
                    const float go = acc[2][mt][nt][2 * h + e];
                    const float gc = acc[3][mt][nt][2 * h + e];
                    const float iv = sigmoidf_(gi);
                    const float fv = sigmoidf_(gf);
                    const float ov = sigmoidf_(go);
                    const float ct = tanhf_(gc);
                    const float pcx = (e == 0) ? pcv.x : pcv.y;
                    const float cc = fv * pcx + iv * ct;
                    cv[e] = cc;
                    hv[e] = ov * tanhf_(cc);
                }
                *(float2*)(oh + n) = make_float2(hv[0], hv[1]);
                *(float2*)(oc + n) = make_float2(cv[0], cv[1]);
            }
        }
}

// ---------------- host launch ----------------
extern "C" void kernel_launch(void* const* d_in, const int* in_sizes, int n_in,
                              void* d_out, int out_size) {
    const float* x      = (const float*)d_in[0];
    const float* prev_h = (const float*)d_in[1];
    const float* prev_c = (const float*)d_in[2];
    const float* Wi     = (const float*)d_in[3];
    const float* Wf     = (const float*)d_in[4];
    const float* Wo     = (const float*)d_in[5];
    const float* Wc     = (const float*)d_in[6];
    float* out = (float*)d_out;

    prep_A<<<2048, 256>>>(x, prev_h);
    prep_W<<<4096, 256>>>(Wi, Wf, Wo, Wc);

    static bool attr_set = false;
    if (!attr_set) {
        cudaFuncSetAttribute(lstm_main, cudaFuncAttributeMaxDynamicSharedMemorySize,
                             SMEM_TOTAL);
        attr_set = true;
    }
    dim3 grid(BDIM / MT, HDIM / NG);   // (32, 32); x-fast -> CTAs sharing weights co-resident
    lstm_main<<<grid, 256, SMEM_TOTAL>>>(prev_c, out);
    (void)in_sizes; (void)n_in; (void)out_size;
}

// round 3
// speedup vs baseline: 1.0498x; 1.0498x over previous
#include <cuda_runtime.h>
#include <cstdint>
#include <math.h>

#define DEVI __device__ __forceinline__

static constexpr int BDIM  = 4096;
static constexpr int INDIM = 1024;
static constexpr int HDIM  = 2048;
static constexpr int KDIM  = HDIM + INDIM;        // 3072
static constexpr int MT  = 128;                   // CTA M tile
static constexpr int NG  = 64;                    // CTA N tile per gate
static constexpr int NTT = 4 * NG;                // 256 total N rows in smem
static constexpr int KT  = 32;                    // K chunk (floats) = 128B row
static constexpr int NCHUNK = KDIM / KT;          // 96
static constexpr int STAGES = 3;
static constexpr int A_BYTES   = MT  * 128;       // 16384
static constexpr int B_BYTES   = NTT * 128;       // 32768
static constexpr int STG_BYTES = A_BYTES + B_BYTES;   // 49152
static constexpr int SMEM_TOTAL = STAGES * STG_BYTES; // 147456

// tf32-rounded, k-permuted scratch (device globals: allocation-free)
__device__ __align__(1024) float g_A[(size_t)BDIM * KDIM];      // [B][K]  (hx concat)
__device__ __align__(1024) float g_W[(size_t)4 * HDIM * KDIM];  // [4][H][K]

// ---------------- helpers ----------------
DEVI uint32_t smem_u32(const void* p) {
    uint32_t a;
    asm("{ .reg .u64 t; cvta.to.shared.u64 t, %1; cvt.u32.u64 %0, t; }" : "=r"(a) : "l"(p));
    return a;
}
DEVI float to_tf32(float x) {
    uint32_t u;
    asm("cvt.rna.tf32.f32 %0, %1;" : "=r"(u) : "f"(x));
    return __uint_as_float(u);
}
DEVI void cp16(uint32_t dst, const float* src) {
    asm volatile("cp.async.cg.shared.global [%0], [%1], 16;" :: "r"(dst), "l"(src) : "memory");
}
DEVI void cp_commit() { asm volatile("cp.async.commit_group;" ::: "memory"); }
DEVI void cp_wait1()  { asm volatile("cp.async.wait_group 1;" ::: "memory"); }
DEVI void cp_wait0()  { asm volatile("cp.async.wait_group 0;" ::: "memory"); }

DEVI float2 lds64(uint32_t a) {
    float2 v;
    asm("ld.shared.v2.f32 {%0,%1}, [%2];" : "=f"(v.x), "=f"(v.y) : "r"(a));
    return v;
}
DEVI void mma8(float* d, float2 alo, float2 ahi, float2 b) {
    asm("mma.sync.aligned.m16n8k8.row.col.f32.tf32.tf32.f32 "
        "{%0,%1,%2,%3}, {%4,%5,%6,%7}, {%8,%9}, {%0,%1,%2,%3};"
        : "+f"(d[0]), "+f"(d[1]), "+f"(d[2]), "+f"(d[3])
        : "r"(__float_as_uint(alo.x)), "r"(__float_as_uint(ahi.x)),
          "r"(__float_as_uint(alo.y)), "r"(__float_as_uint(ahi.y)),
          "r"(__float_as_uint(b.x)),   "r"(__float_as_uint(b.y)));
}
DEVI float sigmoidf_(float x) { return __fdividef(1.0f, 1.0f + __expf(-x)); }
DEVI float tanhf_(float x)    { return 2.0f * sigmoidf_(2.0f * x) - 1.0f; }

// ------------- merged prep: tf32-round + k-permute ([0,4,1,5,2,6,3,7] per k8) -------------
static constexpr int A_GRP = BDIM * (KDIM / 8);          // 1572864
static constexpr int W_GRP = 4 * HDIM * (KDIM / 8);      // 3145728
__global__ void prep_all(const float* __restrict__ x,  const float* __restrict__ ph,
                         const float* __restrict__ Wi, const float* __restrict__ Wf,
                         const float* __restrict__ Wo, const float* __restrict__ Wc) {
    const int total = A_GRP + W_GRP;
    for (int i = blockIdx.x * blockDim.x + threadIdx.x; i < total;
         i += gridDim.x * blockDim.x) {
        const float* src;
        float* dst;
        if (i < A_GRP) {
            int b  = i / (KDIM / 8);
            int k0 = (i - b * (KDIM / 8)) * 8;
            src = (k0 < HDIM) ? (ph + (size_t)b * HDIM + k0)
                              : (x  + (size_t)b * INDIM + (k0 - HDIM));
            dst = g_A + (size_t)b * KDIM + k0;
        } else {
            int j = i - A_GRP;
            const int per_gate = HDIM * (KDIM / 8);
            int g   = j / per_gate;
            int off = j - g * per_gate;
            const float* W = (g == 0) ? Wi : (g == 1) ? Wf : (g == 2) ? Wo : Wc;
            src = W + (size_t)off * 8;
            dst = g_W + (size_t)g * HDIM * KDIM + (size_t)off * 8;
        }
        float4 lo = ((const float4*)src)[0];
        float4 hi = ((const float4*)src)[1];
        ((float4*)dst)[0] = make_float4(to_tf32(lo.x), to_tf32(hi.x), to_tf32(lo.y), to_tf32(hi.y));
        ((float4*)dst)[1] = make_float4(to_tf32(lo.z), to_tf32(hi.z), to_tf32(lo.w), to_tf32(hi.w));
    }
}

// ---------------- main fused LSTM GEMM (mma.sync tf32) ----------------
__global__ __launch_bounds__(256, 1)
void lstm_main(const float* __restrict__ prev_c, float* __restrict__ out) {
    extern __shared__ char smem[];
    const uint32_t sb = smem_u32(smem);
    const int tid  = threadIdx.x;
    const int lane = tid & 31;
    const int wid  = tid >> 5;
    const int warp_m = wid & 1;        // 2 warps over M (64 rows each)
    const int warp_n = wid >> 1;       // 4 warps over N (16 cols/gate each)
    const int q   = lane >> 2;         // 0..7
    const int cid = lane & 3;          // 0..3
    const int m0 = blockIdx.x * MT;
    const int n0 = blockIdx.y * NG;

    // ---- cp.async slot setup (12 x 16B per thread per stage) ----
    const float* a_src[4]; uint32_t a_dst[4];
#pragma unroll
    for (int it = 0; it < 4; it++) {
        int i = tid + 256 * it;
        int row = i >> 3, u = i & 7;
        a_src[it] = g_A + (size_t)(m0 + row) * KDIM + u * 4;
        a_dst[it] = sb + row * 128 + (((u ^ (row & 7))) << 4);
    }
    const float* b_src[8]; uint32_t b_dst[8];
#pragma unroll
    for (int it = 0; it < 8; it++) {
        int i = tid + 256 * it;
        int row = i >> 3, u = i & 7;       // row: gate*64 + n_local
        int gate = row >> 6, nl = row & 63;
        b_src[it] = g_W + ((size_t)gate * HDIM + (n0 + nl)) * KDIM + u * 4;
        b_dst[it] = sb + A_BYTES + row * 128 + (((u ^ (row & 7))) << 4);
    }

    // ---- fragment base addresses (kk-step applied as ^ (kk<<5)) ----
    uint32_t aaddr[4][2];
#pragma unroll
    for (int mt = 0; mt < 4; mt++)
#pragma unroll
        for (int h = 0; h < 2; h++) {
            int row = warp_m * 64 + mt * 16 + q + 8 * h;
            aaddr[mt][h] = sb + row * 128 +
                           ((((cid >> 1) ^ (row & 7))) << 4) + 8 * (cid & 1);
        }
    uint32_t baddr[4][2];
#pragma unroll
    for (int g = 0; g < 4; g++)
#pragma unroll
        for (int nt = 0; nt < 2; nt++) {
            int row = g * 64 + warp_n * 16 + nt * 8 + q;
            baddr[g][nt] = sb + A_BYTES + row * 128 +
                           ((((cid >> 1) ^ (row & 7))) << 4) + 8 * (cid & 1);
        }

    float acc[4][4][2][4];
#pragma unroll
    for (int g = 0; g < 4; g++)
#pragma unroll
        for (int mt = 0; mt < 4; mt++)
#pragma unroll
            for (int nt = 0; nt < 2; nt++)
#pragma unroll
                for (int e = 0; e < 4; e++) acc[g][mt][nt][e] = 0.0f;

    auto load_stage = [&](int chunk, int s) {
        const uint32_t so = (uint32_t)(s * STG_BYTES);
        const int ko = chunk * KT;
#pragma unroll
        for (int it = 0; it < 4; it++) cp16(a_dst[it] + so, a_src[it] + ko);
#pragma unroll
        for (int it = 0; it < 8; it++) cp16(b_dst[it] + so, b_src[it] + ko);
        cp_commit();
    };

    // prologue: stages 0,1
    load_stage(0, 0);
    load_stage(1, 1);

    float2 af[2][4][2], bf[2][4][2];

    for (int c = 0; c < NCHUNK; c++) {
        if (c == NCHUNK - 1) cp_wait0(); else cp_wait1();
        __syncthreads();

        if (c + 2 < NCHUNK) load_stage(c + 2, (c + 2) % STAGES);

        const uint32_t so = (uint32_t)((c % STAGES) * STG_BYTES);
        uint32_t ab[4][2], bb[4][2];
#pragma unroll
        for (int mt = 0; mt < 4; mt++) {
            ab[mt][0] = aaddr[mt][0] + so;
            ab[mt][1] = aaddr[mt][1] + so;
        }
#pragma unroll
        for (int g = 0; g < 4; g++) {
            bb[g][0] = baddr[g][0] + so;
            bb[g][1] = baddr[g][1] + so;
        }

        // prime kk=0 fragments
#pragma unroll
        for (int mt = 0; mt < 4; mt++) {
            af[0][mt][0] = lds64(ab[mt][0]);
            af[0][mt][1] = lds64(ab[mt][1]);
        }
#pragma unroll
        for (int g = 0; g < 4; g++) {
            bf[0][g][0] = lds64(bb[g][0]);
            bf[0][g][1] = lds64(bb[g][1]);
        }

#pragma unroll
        for (int kk = 0; kk < 4; kk++) {
            const int cur = kk & 1, nxt = cur ^ 1;
            if (kk < 3) {
                const uint32_t kx = (uint32_t)((kk + 1) << 5);
#pragma unroll
                for (int mt = 0; mt < 4; mt++) {
                    af[nxt][mt][0] = lds64(ab[mt][0] ^ kx);
                    af[nxt][mt][1] = lds64(ab[mt][1] ^ kx);
                }
#pragma unroll
                for (int g = 0; g < 4; g++) {
                    bf[nxt][g][0] = lds64(bb[g][0] ^ kx);
                    bf[nxt][g][1] = lds64(bb[g][1] ^ kx);
                }
            }
#pragma unroll
            for (int g = 0; g < 4; g++)
#pragma unroll
                for (int nt = 0; nt < 2; nt++)
#pragma unroll
                    for (int mt = 0; mt < 4; mt++)
                        mma8(acc[g][mt][nt], af[cur][mt][0], af[cur][mt][1], bf[cur][g][nt]);
        }
        // no trailing barrier: next iteration's post-wait barrier orders slot reuse
    }

    // -------- fused LSTM epilogue (register-wise across gates) --------
#pragma unroll
    for (int mt = 0; mt < 4; mt++)
#pragma unroll
        for (int h = 0; h < 2; h++) {
            const int b = m0 + warp_m * 64 + mt * 16 + q + 8 * h;
            const float* pc = prev_c + (size_t)b * HDIM;
            float* oh = out + (size_t)b * HDIM;
            float* oc = out + (size_t)(BDIM + b) * HDIM;
#pragma unroll
            for (int nt = 0; nt < 2; nt++) {
                const int n = n0 + warp_n * 16 + nt * 8 + 2 * cid;
                float2 pcv = *(const float2*)(pc + n);
                float hv[2], cv[2];
#pragma unroll
                for (int e = 0; e < 2; e++) {
                    const float gi = acc[0][mt][nt][2 * h + e];
                    const float gf = acc[1][mt][nt][2 * h + e];
                    const float go = acc[2][mt][nt][2 * h + e];
                    const float gc = acc[3][mt][nt][2 * h + e];
                    const float iv = sigmoidf_(gi);
                    const float fv = sigmoidf_(gf);
                    const float ov = sigmoidf_(go);
                    const float ct = tanhf_(gc);
                    const float pcx = (e == 0) ? pcv.x : pcv.y;
                    const float cc = fv * pcx + iv * ct;
                    cv[e] = cc;
                    hv[e] = ov * tanhf_(cc);
                }
                *(float2*)(oh + n) = make_float2(hv[0], hv[1]);
                *(float2*)(oc + n) = make_float2(cv[0], cv[1]);
            }
        }
}

// ---------------- host launch ----------------
extern "C" void kernel_launch(void* const* d_in, const int* in_sizes, int n_in,
                              void* d_out, int out_size) {
    const float* x      = (const float*)d_in[0];
    const float* prev_h = (const float*)d_in[1];
    const float* prev_c = (const float*)d_in[2];
    const float* Wi     = (const float*)d_in[3];
    const float* Wf     = (const float*)d_in[4];
    const float* Wo     = (const float*)d_in[5];
    const float* Wc     = (const float*)d_in[6];
    float* out = (float*)d_out;

    prep_all<<<4608, 256>>>(x, prev_h, Wi, Wf, Wo, Wc);

    static bool attr_set = false;
    if (!attr_set) {
        cudaFuncSetAttribute(lstm_main, cudaFuncAttributeMaxDynamicSharedMemorySize,
                             SMEM_TOTAL);
        attr_set = true;
    }
    dim3 grid(BDIM / MT, HDIM / NG);   // (32, 32); x-fast -> CTAs sharing weights co-resident
    lstm_main<<<grid, 256, SMEM_TOTAL>>>(prev_c, out);
    (void)in_sizes; (void)n_in; (void)out_size;
}